// round 10
// baseline (speedup 1.0000x reference)
#include <cuda_runtime.h>

// SpringMass: B=4096 independent 2-state linear ODEs, T=4096 RK4 steps each.
// Affine scan over time (pass1 compose / pass2 block scan / pass3 replay),
// two 2048-step halves with carried (v,x) state.
//
// R10 change: anti-convoy + warp supply. 256-thread CTAs hold TWO independent
// rows (two 128-thread groups, each with its own 16KB tile and NAMED barrier
// bar.sync id,128). Groups never convoy each other, so each group's scan /
// barrier holes are filled by its co-resident sibling. 7 CTAs/SM = 56 warps
// (needs regs<=36 via launch_bounds(256,7)); grid 2048 ~ 1.98 waves.

#define T_LEN  4096
#define NTHR   256
#define GTHR   128                // threads per row-group
#define HALF   (T_LEN / 2)        // 2048 steps per phase
#define F4C    8                  // input float4 per chunk per half
#define O4C    4                  // output float4 per chunk per half

namespace sm_consts {
constexpr double Cd = 0.1, dd = 0.01;
// A = alpha(k)*I + beta(k)*B, B=[[-C,-k],[1,0]] (deg-4 Taylor of exp(dt B))
constexpr double AL1d = -dd*dd/2.0 + Cd*dd*dd*dd/6.0 - Cd*Cd*dd*dd*dd*dd/24.0;
constexpr double AL2d = dd*dd*dd*dd/24.0;
constexpr double BE0d = dd - Cd*dd*dd/2.0 + Cd*Cd*dd*dd*dd/6.0 - Cd*Cd*Cd*dd*dd*dd*dd/24.0;
constexpr double BE1d = -dd*dd*dd/6.0 + Cd*dd*dd*dd*dd/12.0;
// forcing: g = c0*e1 + c1*B*e1, B*e1 = (-C,1)
constexpr double C00 = dd;
constexpr double C01 = dd*(-dd*dd/6.0 + dd*dd*dd*Cd/24.0);
constexpr double C10 = dd*(dd/2.0 - dd*dd*Cd/6.0 + dd*dd*dd*Cd*Cd/24.0);
constexpr double C11 = dd*(-dd*dd*dd/24.0);

constexpr float AL1 = (float)AL1d;
constexpr float AL2 = (float)AL2d;
constexpr float BE0 = (float)BE0d;
constexpr float BE1 = (float)BE1d;
constexpr float KG10 = (float)(C00 - Cd*C10);   // g1 = KG10 + KG11*k
constexpr float KG11 = (float)(C01 - Cd*C11);
constexpr float KG20 = (float)C10;              // g2 = KG20 + KG21*k
constexpr float KG21 = (float)C11;
constexpr float CF   = 0.1f;
}  // namespace sm_consts

struct Aff { float a11, a12, a21, a22, b1, b2; };

__device__ __forceinline__ Aff compose(const Aff& n, const Aff& o) {
    Aff r;
    r.a11 = fmaf(n.a11, o.a11, n.a12 * o.a21);
    r.a12 = fmaf(n.a11, o.a12, n.a12 * o.a22);
    r.a21 = fmaf(n.a21, o.a11, n.a22 * o.a21);
    r.a22 = fmaf(n.a21, o.a12, n.a22 * o.a22);
    r.b1  = fmaf(n.a11, o.b1, fmaf(n.a12, o.b2, n.b1));
    r.b2  = fmaf(n.a21, o.b1, fmaf(n.a22, o.b2, n.b2));
    return r;
}

__device__ __forceinline__ Aff step_map(float k, float F) {
    using namespace sm_consts;
    Aff s;
    float al = fmaf(fmaf(AL2, k, AL1), k, 1.0f);
    float be = fmaf(BE1, k, BE0);
    s.a11 = fmaf(-CF, be, al);
    s.a12 = -k * be;
    s.a21 = be;
    s.a22 = al;
    s.b1 = F * fmaf(KG11, k, KG10);
    s.b2 = F * fmaf(KG21, k, KG20);
    return s;
}

// advance state, return xddot for this step (computed from NEW state)
__device__ __forceinline__ float step_state(float k, float F, float& v, float& x) {
    using namespace sm_consts;
    float al = fmaf(fmaf(AL2, k, AL1), k, 1.0f);
    float be = fmaf(BE1, k, BE0);
    float A11 = fmaf(-CF, be, al);
    float A12 = -k * be;
    float g1  = fmaf(KG11, k, KG10);
    float g2  = fmaf(KG21, k, KG20);
    float vn = fmaf(A11, v, fmaf(A12, x, F * g1));
    float xn = fmaf(be,  v, fmaf(al,  x, F * g2));
    v = vn; x = xn;
    return fmaf(-k, xn, fmaf(-CF, vn, F));
}

__device__ __forceinline__ Aff shfl_up_aff(const Aff& m, int off) {
    Aff r;
    r.a11 = __shfl_up_sync(0xffffffffu, m.a11, off);
    r.a12 = __shfl_up_sync(0xffffffffu, m.a12, off);
    r.a21 = __shfl_up_sync(0xffffffffu, m.a21, off);
    r.a22 = __shfl_up_sync(0xffffffffu, m.a22, off);
    r.b1  = __shfl_up_sync(0xffffffffu, m.b1,  off);
    r.b2  = __shfl_up_sync(0xffffffffu, m.b2,  off);
    return r;
}

// group-scoped barrier: 128 threads, ids 1/2 (0 is the full-CTA barrier)
__device__ __forceinline__ void group_bar(int grp) {
    asm volatile("bar.sync %0, %1;" :: "r"(grp + 1), "r"(GTHR) : "memory");
}

// smem slot for (chunk c, float4 offset o): XOR swizzle keeps per-chunk
// strided reads conflict-free per 8-lane LDS.128 phase.
__device__ __forceinline__ int slot(int c, int o) {
    return c * F4C + (o ^ (c & 7));
}

__global__ void __launch_bounds__(NTHR, 7)
spring_scan_kernel(const float* __restrict__ in,
                   const float* __restrict__ vinit,
                   const float* __restrict__ xinit,
                   float* __restrict__ out) {
    __shared__ float4 buf2[2][GTHR * F4C];   // 2 x 16 KB half-row tiles
    __shared__ Aff wsum2[2][GTHR / 32];

    const int grp  = threadIdx.x >> 7;       // row-group 0/1 (warps 0-3 / 4-7)
    const int l    = threadIdx.x & (GTHR - 1);
    const int lane = l & 31;
    const int w    = l >> 5;
    const int b    = (blockIdx.x << 1) + grp;

    float4* buf = buf2[grp];
    Aff*   wsum = wsum2[grp];

    const float4* gin  = reinterpret_cast<const float4*>(in + (long)b * T_LEN * 2);
    float4*       gout = reinterpret_cast<float4*>(out + (long)b * T_LEN);

    float vh = vinit[b], xh = xinit[b];    // state entering current half

#pragma unroll 1
    for (int half = 0; half < 2; half++) {
        const float4* gin_h  = gin  + half * (HALF / 2);   // 1024 float4 per half
        float4*       gout_h = gout + half * (HALF / 4);   // 512 float4 per half

        // ---- Stage: coalesced global -> swizzled smem ----
#pragma unroll
        for (int r = 0; r < F4C; r++) {
            int idx = r * GTHR + l;
            buf[slot(idx >> 3, idx & 7)] = gin_h[idx];
        }
        group_bar(grp);

        // ---- Pass 1: compose this thread's 16-step chunk map ----
        Aff M = {1.f, 0.f, 0.f, 1.f, 0.f, 0.f};
#pragma unroll 4
        for (int o = 0; o < F4C; o++) {
            float4 d = buf[slot(l, o)];
            M = compose(step_map(d.x, d.y), M);
            M = compose(step_map(d.z, d.w), M);
        }

        // ---- Pass 2: group-wide scan ----
#pragma unroll
        for (int off = 1; off < 32; off <<= 1) {
            Aff o = shfl_up_aff(M, off);
            if (lane >= off) M = compose(M, o);
        }

        // exclusive in-warp value first (shortens M's live range)
        Aff eo = shfl_up_aff(M, 1);
        Aff excl;
        if (lane == 0) { excl.a11 = 1.f; excl.a12 = 0.f; excl.a21 = 0.f;
                         excl.a22 = 1.f; excl.b1 = 0.f;  excl.b2 = 0.f; }
        else           { excl = eo; }

        if (lane == 31) wsum[w] = M;
        group_bar(grp);

        // prefix over preceding warps + total half map (for the carry)
        Aff pre    = {1.f, 0.f, 0.f, 1.f, 0.f, 0.f};
        Aff preAll = {1.f, 0.f, 0.f, 1.f, 0.f, 0.f};
#pragma unroll
        for (int j = 0; j < GTHR / 32; j++) {
            if (j == w) pre = preAll;
            preAll = compose(wsum[j], preAll);
        }

        Aff tot = compose(excl, pre);      // exclusive prefix within half

        // state entering this thread's chunk
        float v = fmaf(tot.a11, vh, fmaf(tot.a12, xh, tot.b1));
        float x = fmaf(tot.a21, vh, fmaf(tot.a22, xh, tot.b2));

        // carry: state entering the next half
        float vh2 = fmaf(preAll.a11, vh, fmaf(preAll.a12, xh, preAll.b1));
        float xh2 = fmaf(preAll.a21, vh, fmaf(preAll.a22, xh, preAll.b2));
        vh = vh2; xh = xh2;

        // ---- Pass 3: replay chunk, write xddot in place ----
        // Output float4 j consumes input float4s 2j,2j+1; overwrites slot j
        // (j <= 2j: already consumed). Chunks are thread-private, no hazard.
#pragma unroll 2
        for (int j = 0; j < O4C; j++) {
            float4 d0 = buf[slot(l, 2 * j)];
            float4 d1 = buf[slot(l, 2 * j + 1)];
            float4 o4;
            o4.x = step_state(d0.x, d0.y, v, x);
            o4.y = step_state(d0.z, d0.w, v, x);
            o4.z = step_state(d1.x, d1.y, v, x);
            o4.w = step_state(d1.z, d1.w, v, x);
            buf[slot(l, j)] = o4;
        }
        group_bar(grp);

        // ---- Drain: swizzled smem -> coalesced global store ----
#pragma unroll
        for (int r = 0; r < O4C; r++) {
            int idx = r * GTHR + l;
            gout_h[idx] = buf[slot(idx >> 2, idx & 3)];
        }
        if (half == 0) group_bar(grp);     // buf + wsum reuse in next half
    }
}

extern "C" void kernel_launch(void* const* d_in, const int* in_sizes, int n_in,
                              void* d_out, int out_size) {
    const float* in = (const float*)d_in[0];       // (B, T, 2) float32
    const float* vi = (const float*)d_in[1];       // (B, 1)
    const float* xi = (const float*)d_in[2];       // (B, 1)
    float* out = (float*)d_out;                    // (B, T, 1) float32
    const int B = in_sizes[1];                     // 4096
    spring_scan_kernel<<<B / 2, NTHR>>>(in, vi, xi, out);
}

// round 11
// speedup vs baseline: 1.1336x; 1.1336x over previous
#include <cuda_runtime.h>

// SpringMass: B=4096 independent 2-state linear ODEs, T=4096 RK4 steps each.
// Affine scan over time (pass1 compose / pass2 block scan / pass3 replay).
//
// R11: software-pipelined staging. Row split into 4 quarters (1024 steps);
// two 10KB smem tiles double-buffered; cp.async.cg (LDGSTS) prefetches
// quarter q+2 right after draining q, overlapping DRAM with compute.
// Stride-5 float4 padding replaces XOR swizzle (conflict-free chunk LDS).

#define T_LEN   4096
#define NTHR    128
#define QSTEPS  1024              // steps per quarter
#define F4Q     4                 // input float4 per thread per quarter
#define O4Q     2                 // output float4 per thread per quarter
#define SSTR    5                 // padded float4 stride per chunk
#define TILEF4  (NTHR * SSTR)     // 640 float4 = 10.24 KB per buffer

namespace sm_consts {
constexpr double Cd = 0.1, dd = 0.01;
// A = alpha(k)*I + beta(k)*B, B=[[-C,-k],[1,0]] (deg-4 Taylor of exp(dt B))
constexpr double AL1d = -dd*dd/2.0 + Cd*dd*dd*dd/6.0 - Cd*Cd*dd*dd*dd*dd/24.0;
constexpr double AL2d = dd*dd*dd*dd/24.0;
constexpr double BE0d = dd - Cd*dd*dd/2.0 + Cd*Cd*dd*dd*dd/6.0 - Cd*Cd*Cd*dd*dd*dd*dd/24.0;
constexpr double BE1d = -dd*dd*dd/6.0 + Cd*dd*dd*dd*dd/12.0;
// forcing: g = c0*e1 + c1*B*e1, B*e1 = (-C,1)
constexpr double C00 = dd;
constexpr double C01 = dd*(-dd*dd/6.0 + dd*dd*dd*Cd/24.0);
constexpr double C10 = dd*(dd/2.0 - dd*dd*Cd/6.0 + dd*dd*dd*Cd*Cd/24.0);
constexpr double C11 = dd*(-dd*dd*dd/24.0);

constexpr float AL1 = (float)AL1d;
constexpr float AL2 = (float)AL2d;
constexpr float BE0 = (float)BE0d;
constexpr float BE1 = (float)BE1d;
constexpr float KG10 = (float)(C00 - Cd*C10);   // g1 = KG10 + KG11*k
constexpr float KG11 = (float)(C01 - Cd*C11);
constexpr float KG20 = (float)C10;              // g2 = KG20 + KG21*k
constexpr float KG21 = (float)C11;
constexpr float CF   = 0.1f;
}  // namespace sm_consts

struct Aff { float a11, a12, a21, a22, b1, b2; };

__device__ __forceinline__ Aff compose(const Aff& n, const Aff& o) {
    Aff r;
    r.a11 = fmaf(n.a11, o.a11, n.a12 * o.a21);
    r.a12 = fmaf(n.a11, o.a12, n.a12 * o.a22);
    r.a21 = fmaf(n.a21, o.a11, n.a22 * o.a21);
    r.a22 = fmaf(n.a21, o.a12, n.a22 * o.a22);
    r.b1  = fmaf(n.a11, o.b1, fmaf(n.a12, o.b2, n.b1));
    r.b2  = fmaf(n.a21, o.b1, fmaf(n.a22, o.b2, n.b2));
    return r;
}

__device__ __forceinline__ Aff step_map(float k, float F) {
    using namespace sm_consts;
    Aff s;
    float al = fmaf(fmaf(AL2, k, AL1), k, 1.0f);
    float be = fmaf(BE1, k, BE0);
    s.a11 = fmaf(-CF, be, al);
    s.a12 = -k * be;
    s.a21 = be;
    s.a22 = al;
    s.b1 = F * fmaf(KG11, k, KG10);
    s.b2 = F * fmaf(KG21, k, KG20);
    return s;
}

// advance state, return xddot for this step (computed from NEW state)
__device__ __forceinline__ float step_state(float k, float F, float& v, float& x) {
    using namespace sm_consts;
    float al = fmaf(fmaf(AL2, k, AL1), k, 1.0f);
    float be = fmaf(BE1, k, BE0);
    float A11 = fmaf(-CF, be, al);
    float A12 = -k * be;
    float g1  = fmaf(KG11, k, KG10);
    float g2  = fmaf(KG21, k, KG20);
    float vn = fmaf(A11, v, fmaf(A12, x, F * g1));
    float xn = fmaf(be,  v, fmaf(al,  x, F * g2));
    v = vn; x = xn;
    return fmaf(-k, xn, fmaf(-CF, vn, F));
}

__device__ __forceinline__ Aff shfl_up_aff(const Aff& m, int off) {
    Aff r;
    r.a11 = __shfl_up_sync(0xffffffffu, m.a11, off);
    r.a12 = __shfl_up_sync(0xffffffffu, m.a12, off);
    r.a21 = __shfl_up_sync(0xffffffffu, m.a21, off);
    r.a22 = __shfl_up_sync(0xffffffffu, m.a22, off);
    r.b1  = __shfl_up_sync(0xffffffffu, m.b1,  off);
    r.b2  = __shfl_up_sync(0xffffffffu, m.b2,  off);
    return r;
}

// padded smem slot for (chunk c, float4 offset o). Stride 5 makes the
// 8-lane LDS.128 phases of chunk reads (c = lane, o fixed) hit distinct
// bank groups: (5c+o) mod 8 cycles through all residues.
__device__ __forceinline__ int slot(int c, int o) {
    return c * SSTR + o;
}

__device__ __forceinline__ void cp16(float4* smem_dst, const float4* gsrc) {
    unsigned s = (unsigned)__cvta_generic_to_shared(smem_dst);
    asm volatile("cp.async.cg.shared.global [%0], [%1], 16;" :: "r"(s), "l"(gsrc));
}
__device__ __forceinline__ void cp_commit() {
    asm volatile("cp.async.commit_group;" ::: "memory");
}
template <int N>
__device__ __forceinline__ void cp_wait() {
    asm volatile("cp.async.wait_group %0;" :: "n"(N) : "memory");
}

__global__ void __launch_bounds__(NTHR, 11)
spring_scan_kernel(const float* __restrict__ in,
                   const float* __restrict__ vinit,
                   const float* __restrict__ xinit,
                   float* __restrict__ out) {
    __shared__ float4 buf2[2][TILEF4];     // double-buffered quarter tiles
    __shared__ Aff wsum[NTHR / 32];

    const int b = blockIdx.x;
    const int l = threadIdx.x;
    const int lane = l & 31;
    const int w = l >> 5;

    const float4* gin  = reinterpret_cast<const float4*>(in + (long)b * T_LEN * 2);
    float4*       gout = reinterpret_cast<float4*>(out + (long)b * T_LEN);

    float vh = vinit[b], xh = xinit[b];    // state entering current quarter

    // ---- Prologue: prefetch quarters 0 and 1 ----
#pragma unroll
    for (int q = 0; q < 2; q++) {
        const float4* g = gin + q * (QSTEPS / 2);
        float4* buf = buf2[q];
#pragma unroll
        for (int r = 0; r < F4Q; r++) {
            int idx = r * NTHR + l;
            cp16(&buf[slot(idx >> 2, idx & 3)], &g[idx]);
        }
        cp_commit();
    }

#pragma unroll 1
    for (int q = 0; q < 4; q++) {
        float4* buf = buf2[q & 1];
        float4* gout_q = gout + q * (QSTEPS / 4);

        // wait for quarter q's tile (allow the q+1 group to stay in flight)
        if (q < 3) cp_wait<1>(); else cp_wait<0>();
        __syncthreads();

        // ---- Pass 1: compose this thread's 8-step chunk map ----
        Aff M = {1.f, 0.f, 0.f, 1.f, 0.f, 0.f};
#pragma unroll
        for (int o = 0; o < F4Q; o++) {
            float4 d = buf[slot(l, o)];
            M = compose(step_map(d.x, d.y), M);
            M = compose(step_map(d.z, d.w), M);
        }

        // ---- Pass 2: block-wide scan ----
#pragma unroll
        for (int off = 1; off < 32; off <<= 1) {
            Aff o = shfl_up_aff(M, off);
            if (lane >= off) M = compose(M, o);
        }

        Aff eo = shfl_up_aff(M, 1);
        Aff excl;
        if (lane == 0) { excl.a11 = 1.f; excl.a12 = 0.f; excl.a21 = 0.f;
                         excl.a22 = 1.f; excl.b1 = 0.f;  excl.b2 = 0.f; }
        else           { excl = eo; }

        if (lane == 31) wsum[w] = M;
        __syncthreads();

        Aff pre    = {1.f, 0.f, 0.f, 1.f, 0.f, 0.f};
        Aff preAll = {1.f, 0.f, 0.f, 1.f, 0.f, 0.f};
#pragma unroll
        for (int j = 0; j < NTHR / 32; j++) {
            if (j == w) pre = preAll;
            preAll = compose(wsum[j], preAll);
        }

        Aff tot = compose(excl, pre);      // exclusive prefix within quarter

        // state entering this thread's chunk
        float v = fmaf(tot.a11, vh, fmaf(tot.a12, xh, tot.b1));
        float x = fmaf(tot.a21, vh, fmaf(tot.a22, xh, tot.b2));

        // carry: state entering the next quarter
        float vh2 = fmaf(preAll.a11, vh, fmaf(preAll.a12, xh, preAll.b1));
        float xh2 = fmaf(preAll.a21, vh, fmaf(preAll.a22, xh, preAll.b2));
        vh = vh2; xh = xh2;

        // ---- Pass 3: replay chunk, write xddot in place (thread-private) ----
#pragma unroll
        for (int j = 0; j < O4Q; j++) {
            float4 d0 = buf[slot(l, 2 * j)];
            float4 d1 = buf[slot(l, 2 * j + 1)];
            float4 o4;
            o4.x = step_state(d0.x, d0.y, v, x);
            o4.y = step_state(d0.z, d0.w, v, x);
            o4.z = step_state(d1.x, d1.y, v, x);
            o4.w = step_state(d1.z, d1.w, v, x);
            buf[slot(l, j)] = o4;
        }
        __syncthreads();                   // pass3 writes visible to drain

        // ---- Drain: padded smem -> coalesced global store ----
#pragma unroll
        for (int r = 0; r < O4Q; r++) {
            int idx = r * NTHR + l;
            gout_q[idx] = buf[slot(idx >> 1, idx & 1)];
        }

        // ---- Prefetch quarter q+2 into this buffer (after drain reads) ----
        if (q < 2) {
            __syncthreads();               // all drain LDS done before overwrite
            const float4* g = gin + (q + 2) * (QSTEPS / 2);
#pragma unroll
            for (int r = 0; r < F4Q; r++) {
                int idx = r * NTHR + l;
                cp16(&buf[slot(idx >> 2, idx & 3)], &g[idx]);
            }
            cp_commit();
        }
    }
}

extern "C" void kernel_launch(void* const* d_in, const int* in_sizes, int n_in,
                              void* d_out, int out_size) {
    const float* in = (const float*)d_in[0];       // (B, T, 2) float32
    const float* vi = (const float*)d_in[1];       // (B, 1)
    const float* xi = (const float*)d_in[2];       // (B, 1)
    float* out = (float*)d_out;                    // (B, T, 1) float32
    const int B = in_sizes[1];                     // 4096
    spring_scan_kernel<<<B, NTHR>>>(in, vi, xi, out);
}

// round 12
// speedup vs baseline: 1.2066x; 1.0645x over previous
#include <cuda_runtime.h>

// SpringMass: B=4096 independent 2-state linear ODEs, T=4096 RK4 steps each.
// Affine scan over time (pass1 compose / pass2 scan / pass3 replay).
//
// R12 = R11 (cp.async depth-2 pipelined quarters, issue 73.5%) + scan surgery:
// cross-warp prefix handled by APPLYING warp-sum maps to the carried state
// (4 FMA per map) instead of COMPOSING maps (12 FMA per map) and then
// applying. Saves ~46 instr per scan, ~184 per thread (~10%).

#define T_LEN   4096
#define NTHR    128
#define QSTEPS  1024              // steps per quarter
#define F4Q     4                 // input float4 per thread per quarter
#define O4Q     2                 // output float4 per thread per quarter
#define SSTR    5                 // padded float4 stride per chunk
#define TILEF4  (NTHR * SSTR)     // 640 float4 = 10.24 KB per buffer

namespace sm_consts {
constexpr double Cd = 0.1, dd = 0.01;
// A = alpha(k)*I + beta(k)*B, B=[[-C,-k],[1,0]] (deg-4 Taylor of exp(dt B))
constexpr double AL1d = -dd*dd/2.0 + Cd*dd*dd*dd/6.0 - Cd*Cd*dd*dd*dd*dd/24.0;
constexpr double AL2d = dd*dd*dd*dd/24.0;
constexpr double BE0d = dd - Cd*dd*dd/2.0 + Cd*Cd*dd*dd*dd/6.0 - Cd*Cd*Cd*dd*dd*dd*dd/24.0;
constexpr double BE1d = -dd*dd*dd/6.0 + Cd*dd*dd*dd*dd/12.0;
// forcing: g = c0*e1 + c1*B*e1, B*e1 = (-C,1)
constexpr double C00 = dd;
constexpr double C01 = dd*(-dd*dd/6.0 + dd*dd*dd*Cd/24.0);
constexpr double C10 = dd*(dd/2.0 - dd*dd*Cd/6.0 + dd*dd*dd*Cd*Cd/24.0);
constexpr double C11 = dd*(-dd*dd*dd/24.0);

constexpr float AL1 = (float)AL1d;
constexpr float AL2 = (float)AL2d;
constexpr float BE0 = (float)BE0d;
constexpr float BE1 = (float)BE1d;
constexpr float KG10 = (float)(C00 - Cd*C10);   // g1 = KG10 + KG11*k
constexpr float KG11 = (float)(C01 - Cd*C11);
constexpr float KG20 = (float)C10;              // g2 = KG20 + KG21*k
constexpr float KG21 = (float)C11;
constexpr float CF   = 0.1f;
}  // namespace sm_consts

struct Aff { float a11, a12, a21, a22, b1, b2; };

__device__ __forceinline__ Aff compose(const Aff& n, const Aff& o) {
    Aff r;
    r.a11 = fmaf(n.a11, o.a11, n.a12 * o.a21);
    r.a12 = fmaf(n.a11, o.a12, n.a12 * o.a22);
    r.a21 = fmaf(n.a21, o.a11, n.a22 * o.a21);
    r.a22 = fmaf(n.a21, o.a12, n.a22 * o.a22);
    r.b1  = fmaf(n.a11, o.b1, fmaf(n.a12, o.b2, n.b1));
    r.b2  = fmaf(n.a21, o.b1, fmaf(n.a22, o.b2, n.b2));
    return r;
}

// apply affine map to state: s' = A s + b   (4 FMA)
__device__ __forceinline__ void apply(const Aff& m, float& v, float& x) {
    float vn = fmaf(m.a11, v, fmaf(m.a12, x, m.b1));
    float xn = fmaf(m.a21, v, fmaf(m.a22, x, m.b2));
    v = vn; x = xn;
}

__device__ __forceinline__ Aff step_map(float k, float F) {
    using namespace sm_consts;
    Aff s;
    float al = fmaf(fmaf(AL2, k, AL1), k, 1.0f);
    float be = fmaf(BE1, k, BE0);
    s.a11 = fmaf(-CF, be, al);
    s.a12 = -k * be;
    s.a21 = be;
    s.a22 = al;
    s.b1 = F * fmaf(KG11, k, KG10);
    s.b2 = F * fmaf(KG21, k, KG20);
    return s;
}

// advance state, return xddot for this step (computed from NEW state)
__device__ __forceinline__ float step_state(float k, float F, float& v, float& x) {
    using namespace sm_consts;
    float al = fmaf(fmaf(AL2, k, AL1), k, 1.0f);
    float be = fmaf(BE1, k, BE0);
    float A11 = fmaf(-CF, be, al);
    float A12 = -k * be;
    float g1  = fmaf(KG11, k, KG10);
    float g2  = fmaf(KG21, k, KG20);
    float vn = fmaf(A11, v, fmaf(A12, x, F * g1));
    float xn = fmaf(be,  v, fmaf(al,  x, F * g2));
    v = vn; x = xn;
    return fmaf(-k, xn, fmaf(-CF, vn, F));
}

__device__ __forceinline__ Aff shfl_up_aff(const Aff& m, int off) {
    Aff r;
    r.a11 = __shfl_up_sync(0xffffffffu, m.a11, off);
    r.a12 = __shfl_up_sync(0xffffffffu, m.a12, off);
    r.a21 = __shfl_up_sync(0xffffffffu, m.a21, off);
    r.a22 = __shfl_up_sync(0xffffffffu, m.a22, off);
    r.b1  = __shfl_up_sync(0xffffffffu, m.b1,  off);
    r.b2  = __shfl_up_sync(0xffffffffu, m.b2,  off);
    return r;
}

// padded smem slot for (chunk c, float4 offset o); stride 5 keeps the 8-lane
// LDS.128 phases of chunk reads conflict-free.
__device__ __forceinline__ int slot(int c, int o) {
    return c * SSTR + o;
}

__device__ __forceinline__ void cp16(float4* smem_dst, const float4* gsrc) {
    unsigned s = (unsigned)__cvta_generic_to_shared(smem_dst);
    asm volatile("cp.async.cg.shared.global [%0], [%1], 16;" :: "r"(s), "l"(gsrc));
}
__device__ __forceinline__ void cp_commit() {
    asm volatile("cp.async.commit_group;" ::: "memory");
}
template <int N>
__device__ __forceinline__ void cp_wait() {
    asm volatile("cp.async.wait_group %0;" :: "n"(N) : "memory");
}

__global__ void __launch_bounds__(NTHR, 11)
spring_scan_kernel(const float* __restrict__ in,
                   const float* __restrict__ vinit,
                   const float* __restrict__ xinit,
                   float* __restrict__ out) {
    __shared__ float4 buf2[2][TILEF4];     // double-buffered quarter tiles
    __shared__ Aff wsum[NTHR / 32];

    const int b = blockIdx.x;
    const int l = threadIdx.x;
    const int lane = l & 31;
    const int w = l >> 5;

    const float4* gin  = reinterpret_cast<const float4*>(in + (long)b * T_LEN * 2);
    float4*       gout = reinterpret_cast<float4*>(out + (long)b * T_LEN);

    float vh = vinit[b], xh = xinit[b];    // state entering current quarter

    // ---- Prologue: prefetch quarters 0 and 1 ----
#pragma unroll
    for (int q = 0; q < 2; q++) {
        const float4* g = gin + q * (QSTEPS / 2);
        float4* buf = buf2[q];
#pragma unroll
        for (int r = 0; r < F4Q; r++) {
            int idx = r * NTHR + l;
            cp16(&buf[slot(idx >> 2, idx & 3)], &g[idx]);
        }
        cp_commit();
    }

#pragma unroll 1
    for (int q = 0; q < 4; q++) {
        float4* buf = buf2[q & 1];
        float4* gout_q = gout + q * (QSTEPS / 4);

        // wait for quarter q's tile (allow the q+1 group to stay in flight)
        if (q < 3) cp_wait<1>(); else cp_wait<0>();
        __syncthreads();

        // ---- Pass 1: compose this thread's 8-step chunk map ----
        Aff M = {1.f, 0.f, 0.f, 1.f, 0.f, 0.f};
#pragma unroll
        for (int o = 0; o < F4Q; o++) {
            float4 d = buf[slot(l, o)];
            M = compose(step_map(d.x, d.y), M);
            M = compose(step_map(d.z, d.w), M);
        }

        // ---- Pass 2: warp scan of chunk maps ----
#pragma unroll
        for (int off = 1; off < 32; off <<= 1) {
            Aff o = shfl_up_aff(M, off);
            if (lane >= off) M = compose(M, o);
        }

        // exclusive in-warp map
        Aff eo = shfl_up_aff(M, 1);
        Aff excl;
        if (lane == 0) { excl.a11 = 1.f; excl.a12 = 0.f; excl.a21 = 0.f;
                         excl.a22 = 1.f; excl.b1 = 0.f;  excl.b2 = 0.f; }
        else           { excl = eo; }

        if (lane == 31) wsum[w] = M;
        __syncthreads();

        // ---- Cross-warp: run the carried STATE through warp-sum maps ----
        // (affine apply = 4 FMA vs map compose = 12 FMA)
        float sv = vh, sx = xh;            // running state
        float pv = vh, px = xh;            // state entering this warp
#pragma unroll
        for (int j = 0; j < NTHR / 32; j++) {
            if (j == w) { pv = sv; px = sx; }
            apply(wsum[j], sv, sx);
        }
        vh = sv; xh = sx;                  // carry: state entering next quarter

        // state entering this thread's chunk
        float v = pv, x = px;
        apply(excl, v, x);

        // ---- Pass 3: replay chunk, write xddot in place (thread-private) ----
#pragma unroll
        for (int j = 0; j < O4Q; j++) {
            float4 d0 = buf[slot(l, 2 * j)];
            float4 d1 = buf[slot(l, 2 * j + 1)];
            float4 o4;
            o4.x = step_state(d0.x, d0.y, v, x);
            o4.y = step_state(d0.z, d0.w, v, x);
            o4.z = step_state(d1.x, d1.y, v, x);
            o4.w = step_state(d1.z, d1.w, v, x);
            buf[slot(l, j)] = o4;
        }
        __syncthreads();                   // pass3 writes visible to drain

        // ---- Drain: padded smem -> coalesced global store ----
#pragma unroll
        for (int r = 0; r < O4Q; r++) {
            int idx = r * NTHR + l;
            gout_q[idx] = buf[slot(idx >> 1, idx & 1)];
        }

        // ---- Prefetch quarter q+2 into this buffer (after drain reads) ----
        if (q < 2) {
            __syncthreads();               // all drain LDS done before overwrite
            const float4* g = gin + (q + 2) * (QSTEPS / 2);
#pragma unroll
            for (int r = 0; r < F4Q; r++) {
                int idx = r * NTHR + l;
                cp16(&buf[slot(idx >> 2, idx & 3)], &g[idx]);
            }
            cp_commit();
        }
    }
}

extern "C" void kernel_launch(void* const* d_in, const int* in_sizes, int n_in,
                              void* d_out, int out_size) {
    const float* in = (const float*)d_in[0];       // (B, T, 2) float32
    const float* vi = (const float*)d_in[1];       // (B, 1)
    const float* xi = (const float*)d_in[2];       // (B, 1)
    float* out = (float*)d_out;                    // (B, T, 1) float32
    const int B = in_sizes[1];                     // 4096
    spring_scan_kernel<<<B, NTHR>>>(in, vi, xi, out);
}